// round 11
// baseline (speedup 1.0000x reference)
#include <cuda_runtime.h>
#include <cuda_bf16.h>
#include <cuda_fp16.h>
#include <stdint.h>
#include <math.h>

#define NS 16384
#define ND 2048
#define NC 1000
#define NCP 1024

#define MARGIN 1.5f

// GEMM tiling: 128x128 block, 8 warps (4x2), warp tile 32x64, 2 CTAs/SM
#define BM 128
#define BN 128
#define BK 64                  // K per chunk: 128 bytes/row (SW128 atom)
#define KCHUNKS (ND / BK)      // 32
#define STAGES 3
#define A_TILE_BYTES (BM * BK * 2)   // 16384
#define B_TILE_BYTES (BN * BK * 2)   // 16384
#define STAGE_BYTES (A_TILE_BYTES + B_TILE_BYTES)  // 32768
#define SMEM_TOTAL (STAGES * STAGE_BYTES + 1024)

#define NBN (NCP / BN)         // 8 partials per row

// ---------------- scratch (static device globals) ---------------------------
__device__ __nv_bfloat16 g_xb[(size_t)NS * ND];    // tiled: [bm][kt][128x64 SW128]
__device__ __nv_bfloat16 g_mb[(size_t)NCP * ND];   // tiled: [bn][kt][128x64 SW128]
__device__ __half        g_scores[(size_t)NS * NCP];
__device__ float         g_pmax[(size_t)NS * NBN];
__device__ float         g_psnd[(size_t)NS * NBN];
__device__ int           g_pidx[(size_t)NS * NBN];
__device__ int           g_pred[NS];
__device__ float         g_thr[NS];
__device__ int           g_refine_list[NS];
__device__ int           g_refine_cnt;

// ---------------- helpers ----------------------------------------------------
__device__ __forceinline__ uint32_t smem_u32(const void* p) {
    return (uint32_t)__cvta_generic_to_shared(p);
}
__host__ __device__ __forceinline__ uint32_t sw128(uint32_t off) {
    return off ^ ((off >> 3) & 0x70);
}
__device__ __forceinline__ void cp16(uint32_t dst, const void* src) {
    asm volatile("cp.async.cg.shared.global [%0], [%1], 16;"
                 :: "r"(dst), "l"(src) : "memory");
}
__device__ __forceinline__ void cp_commit() {
    asm volatile("cp.async.commit_group;" ::: "memory");
}
template <int N>
__device__ __forceinline__ void cp_wait() {
    asm volatile("cp.async.wait_group %0;" :: "n"(N) : "memory");
}
__device__ __forceinline__ void ldsm_x4(uint32_t& r0, uint32_t& r1, uint32_t& r2,
                                        uint32_t& r3, uint32_t addr) {
    asm volatile("ldmatrix.sync.aligned.m8n8.x4.shared.b16 {%0,%1,%2,%3}, [%4];\n"
                 : "=r"(r0), "=r"(r1), "=r"(r2), "=r"(r3) : "r"(addr));
}
__device__ __forceinline__ void mma_bf16(float* c, const uint32_t* a, const uint32_t* b) {
    asm volatile(
        "mma.sync.aligned.m16n8k16.row.col.f32.bf16.bf16.f32 "
        "{%0,%1,%2,%3}, {%4,%5,%6,%7}, {%8,%9}, {%0,%1,%2,%3};\n"
        : "+f"(c[0]), "+f"(c[1]), "+f"(c[2]), "+f"(c[3])
        : "r"(a[0]), "r"(a[1]), "r"(a[2]), "r"(a[3]), "r"(b[0]), "r"(b[1]));
}
// combine (max, idx, second) partials; prefer larger val, then smaller idx
__device__ __forceinline__ void comb(float& m, int& id, float& s,
                                     float om, int oid, float os) {
    if (om > m || (om == m && oid < id)) {
        s = fmaxf(m, os); m = om; id = oid;
    } else {
        s = fmaxf(s, om);
    }
}

// ---------------- convert kernels: tile-linear (coalesced) SW128 writes -----
// chunk g -> tile (g>>10), within-tile 16B chunk w (g&1023): r=w>>3, cgrp=w&7.
// dest = tile*16KB + sw128(w*16): sw128 permutes 16B chunks only WITHIN each
// 128B line (bits 4-6 ^= bits 7-9), so warp writes are full 128B lines.
__global__ __launch_bounds__(256) void cvt_x_kernel(const float4* __restrict__ x) {
    uint32_t g = blockIdx.x * 256 + threadIdx.x;   // 0 .. NS*ND/8-1 (4,194,304)
    uint32_t tile = g >> 10;                       // [bm(128)][kt(32)]
    uint32_t w    = g & 1023;
    uint32_t tm = tile >> 5, tk = tile & 31;
    uint32_t r  = w >> 3, cgrp = w & 7;
    uint32_t row = tm * 128 + r;
    // x in float4 units: row stride 512, k-chunk 16, cgrp 2
    size_t src = (size_t)row * 512 + tk * 16 + cgrp * 2;
    float4 v0 = x[src];
    float4 v1 = x[src + 1];
    __nv_bfloat162 b0 = __floats2bfloat162_rn(v0.x, v0.y);
    __nv_bfloat162 b1 = __floats2bfloat162_rn(v0.z, v0.w);
    __nv_bfloat162 b2 = __floats2bfloat162_rn(v1.x, v1.y);
    __nv_bfloat162 b3 = __floats2bfloat162_rn(v1.z, v1.w);
    uint4 q;
    q.x = *reinterpret_cast<uint32_t*>(&b0);
    q.y = *reinterpret_cast<uint32_t*>(&b1);
    q.z = *reinterpret_cast<uint32_t*>(&b2);
    q.w = *reinterpret_cast<uint32_t*>(&b3);
    *reinterpret_cast<uint4*>((char*)g_xb + (size_t)tile * A_TILE_BYTES +
                              sw128(w * 16)) = q;
    if (g == 0) g_refine_cnt = 0;
}

__global__ __launch_bounds__(256) void cvt_m_kernel(const float4* __restrict__ m) {
    uint32_t g = blockIdx.x * 256 + threadIdx.x;   // 0 .. NCP*ND/8-1 (524,288)
    uint32_t tile = g >> 10;                       // [bn(8)][kt(32)]
    uint32_t w    = g & 1023;
    uint32_t tb = tile >> 5, tk = tile & 31;
    uint32_t r  = w >> 3, cgrp = w & 7;
    uint32_t row = tb * 128 + r;
    float4 v0 = make_float4(0.f, 0.f, 0.f, 0.f), v1 = v0;
    if (row < NC) {
        size_t src = (size_t)row * 512 + tk * 16 + cgrp * 2;
        v0 = m[src];
        v1 = m[src + 1];
    }
    __nv_bfloat162 b0 = __floats2bfloat162_rn(v0.x, v0.y);
    __nv_bfloat162 b1 = __floats2bfloat162_rn(v0.z, v0.w);
    __nv_bfloat162 b2 = __floats2bfloat162_rn(v1.x, v1.y);
    __nv_bfloat162 b3 = __floats2bfloat162_rn(v1.z, v1.w);
    uint4 q;
    q.x = *reinterpret_cast<uint32_t*>(&b0);
    q.y = *reinterpret_cast<uint32_t*>(&b1);
    q.z = *reinterpret_cast<uint32_t*>(&b2);
    q.w = *reinterpret_cast<uint32_t*>(&b3);
    *reinterpret_cast<uint4*>((char*)g_mb + (size_t)tile * B_TILE_BYTES +
                              sw128(w * 16)) = q;
}

// ---------------- zero output (3rd launch; GEMM must be 4th for ncu) --------
__global__ __launch_bounds__(256) void zero_out_kernel(float4* __restrict__ out) {
    const size_t n4 = (size_t)NS * NC / 4;
    for (size_t i = (size_t)blockIdx.x * 256 + threadIdx.x; i < n4;
         i += (size_t)gridDim.x * 256)
        out[i] = make_float4(0.f, 0.f, 0.f, 0.f);
}

// ---------------- GEMM: 128x128 block, 8 warps 4x2, warp 32x64 --------------
// Cross-chunk fragment prefetch: the wait+barrier sits at ks=3 and next
// chunk's ks=0 fragments are loaded in the shadow of ks=3's MMAs.
__global__ __launch_bounds__(256, 2) void gemm_mma7_kernel() {
    extern __shared__ char smem[];
    const uint32_t sb = (smem_u32(smem) + 1023u) & ~1023u;

    const int tid  = threadIdx.x;
    const int lane = tid & 31;
    const int wid  = tid >> 5;
    const int wm   = wid >> 1;   // 0..3 -> 32-row slab
    const int wn   = wid & 1;    // 0..1 -> 64-col slab
    const int bn   = blockIdx.x; // 0..7
    const int bm   = blockIdx.y; // 0..127

    const char* gA = (const char*)g_xb + (size_t)bm * KCHUNKS * A_TILE_BYTES;
    const char* gB = (const char*)g_mb + (size_t)bn * KCHUNKS * B_TILE_BYTES;

    auto load_stage = [&](int s, int kt) {
        uint32_t Ad = sb + s * STAGE_BYTES;
        const char* Asrc = gA + (size_t)kt * A_TILE_BYTES;
        #pragma unroll
        for (int i = 0; i < 4; i++) {
            int ch = tid + i * 256;
            cp16(Ad + ch * 16, Asrc + ch * 16);
        }
        uint32_t Bd = Ad + A_TILE_BYTES;
        const char* Bsrc = gB + (size_t)kt * B_TILE_BYTES;
        #pragma unroll
        for (int i = 0; i < 4; i++) {
            int ch = tid + i * 256;
            cp16(Bd + ch * 16, Bsrc + ch * 16);
        }
    };

    float acc[2][8][4];
    #pragma unroll
    for (int i = 0; i < 2; i++)
        #pragma unroll
        for (int j = 0; j < 8; j++)
            #pragma unroll
            for (int k = 0; k < 4; k++) acc[i][j][k] = 0.f;

    load_stage(0, 0); cp_commit();
    load_stage(1, 1); cp_commit();

    const int a_row = wm * 32 + (lane & 15);
    const int a_kb  = ((lane >> 4) << 3) * 2;
    const int b_row = wn * 64 + ((lane >> 4) << 3) + (lane & 7);
    const int b_kb  = (((lane >> 3) & 1) << 3) * 2;

    uint32_t afr[2][2][4];
    uint32_t bfr[2][8][2];

    auto frag_load = [&](uint32_t Ab, uint32_t Bb, int ks, int buf) {
        #pragma unroll
        for (int mt = 0; mt < 2; mt++) {
            uint32_t off = (uint32_t)((a_row + mt * 16) * 128 + ks * 32 + a_kb);
            ldsm_x4(afr[buf][mt][0], afr[buf][mt][1], afr[buf][mt][2],
                    afr[buf][mt][3], Ab + sw128(off));
        }
        #pragma unroll
        for (int nb = 0; nb < 4; nb++) {
            uint32_t off = (uint32_t)((b_row + nb * 16) * 128 + ks * 32 + b_kb);
            uint32_t r0, r1, r2, r3;
            ldsm_x4(r0, r1, r2, r3, Bb + sw128(off));
            bfr[buf][nb * 2 + 0][0] = r0; bfr[buf][nb * 2 + 0][1] = r1;
            bfr[buf][nb * 2 + 1][0] = r2; bfr[buf][nb * 2 + 1][1] = r3;
        }
    };

    // stage 0 ready for everyone, then preload (kt=0, ks=0) fragments
    cp_wait<1>();
    __syncthreads();
    frag_load(sb, sb + A_TILE_BYTES, 0, 0);

    for (int kt = 0; kt < KCHUNKS; kt++) {
        // safe: all warps passed the ks=3 barrier of iter kt-1, so nobody is
        // still reading stage (kt-1)%3, which (kt+2)%3 aliases.
        if (kt + 2 < KCHUNKS) { load_stage((kt + 2) % STAGES, kt + 2); cp_commit(); }

        const uint32_t Ab  = sb + (kt % STAGES) * STAGE_BYTES;
        const uint32_t Bb  = Ab + A_TILE_BYTES;
        const uint32_t Abn = sb + ((kt + 1) % STAGES) * STAGE_BYTES;
        const uint32_t Bbn = Abn + A_TILE_BYTES;

        #pragma unroll
        for (int ks = 0; ks < 4; ks++) {
            const int cur = ks & 1;
            if (ks < 3) {
                frag_load(Ab, Bb, ks + 1, cur ^ 1);
            } else if (kt + 1 < KCHUNKS) {
                // pending groups here: {kt+1, kt+2} (kt+2 absent on last iters)
                if (kt == KCHUNKS - 2) cp_wait<0>(); else cp_wait<1>();
                __syncthreads();   // make all threads' stage-(kt+1) copies visible
                frag_load(Abn, Bbn, 0, cur ^ 1);
            }
            #pragma unroll
            for (int mt = 0; mt < 2; mt++)
                #pragma unroll
                for (int nt = 0; nt < 8; nt++)
                    mma_bf16(acc[mt][nt], afr[cur][mt], bfr[cur][nt]);
        }
    }

    // ---------------- epilogue: store fp16 scores + per-row (max,idx,second) -
    #pragma unroll
    for (int mt = 0; mt < 2; mt++) {
        #pragma unroll
        for (int nt = 0; nt < 8; nt++) {
            int row = bm * BM + wm * 32 + mt * 16 + (lane >> 2);
            int col = bn * BN + wn * 64 + nt * 8 + ((lane & 3) << 1);
            *reinterpret_cast<__half2*>(&g_scores[(size_t)row * NCP + col]) =
                __floats2half2_rn(acc[mt][nt][0], acc[mt][nt][1]);
            *reinterpret_cast<__half2*>(&g_scores[(size_t)(row + 8) * NCP + col]) =
                __floats2half2_rn(acc[mt][nt][2], acc[mt][nt][3]);
        }
    }

    __syncthreads();   // stage buffers dead; reuse smem for partial reduction
    float* pm = reinterpret_cast<float*>(smem);        // [2][128]
    float* ps = pm + 256;                              // [2][128]
    int*   pi = reinterpret_cast<int*>(ps + 256);      // [2][128]

    const int cbase = bn * BN + wn * 64 + ((lane & 3) << 1);
    #pragma unroll
    for (int mt = 0; mt < 2; mt++) {
        #pragma unroll
        for (int h = 0; h < 2; h++) {
            float m = -INFINITY, s = -INFINITY;
            int   id = 0;
            #pragma unroll
            for (int nt = 0; nt < 8; nt++) {
                #pragma unroll
                for (int e = 0; e < 2; e++) {
                    int   col = cbase + nt * 8 + e;
                    float v   = acc[mt][nt][h * 2 + e];
                    if (col >= NC) v = -INFINITY;
                    if (v > m) { s = m; m = v; id = col; }
                    else if (v > s) s = v;
                }
            }
            // quad reduce across the 4 lanes sharing this row
            #pragma unroll
            for (int x = 1; x <= 2; x <<= 1) {
                float om = __shfl_xor_sync(0xffffffffu, m, x);
                int   oi = __shfl_xor_sync(0xffffffffu, id, x);
                float os = __shfl_xor_sync(0xffffffffu, s, x);
                comb(m, id, s, om, oi, os);
            }
            if ((lane & 3) == 0) {
                int rl = wm * 32 + mt * 16 + h * 8 + (lane >> 2);
                pm[wn * 128 + rl] = m;
                ps[wn * 128 + rl] = s;
                pi[wn * 128 + rl] = id;
            }
        }
    }
    __syncthreads();

    if (tid < 128) {
        float m = pm[tid];      int id = pi[tid];      float s = ps[tid];
        comb(m, id, s, pm[128 + tid], pi[128 + tid], ps[128 + tid]);
        size_t o = (size_t)(bm * BM + tid) * NBN + bn;
        g_pmax[o] = m; g_psnd[o] = s; g_pidx[o] = id;
    }
}

// ---------------- combine partials -> pred/thr + write unflagged one-hot ----
__global__ __launch_bounds__(256) void argmax_combine_kernel(float* __restrict__ out) {
    const int s = blockIdx.x * 256 + threadIdx.x;
    if (s >= NS) return;
    const size_t base = (size_t)s * NBN;
    float m = g_pmax[base];  int id = g_pidx[base];  float snd = g_psnd[base];
    #pragma unroll
    for (int p = 1; p < NBN; p++)
        comb(m, id, snd, g_pmax[base + p], g_pidx[base + p], g_psnd[base + p]);

    const float thr = m - MARGIN;
    if (snd >= thr) {
        g_pred[s] = id;
        g_thr[s]  = thr;
        int p = atomicAdd(&g_refine_cnt, 1);
        g_refine_list[p] = s;
    } else {
        out[(size_t)s * NC + id] = 1.0f;   // no competitor within margin
    }
}

// ---------------- exact fp64 refinement + one-hot for flagged samples -------
__global__ __launch_bounds__(256) void refine_kernel(
    const float* __restrict__ x, const float* __restrict__ means,
    float* __restrict__ out) {
    const int tid = threadIdx.x;
    __shared__ int    cnt;
    __shared__ int    cand[33];
    __shared__ double red[8];
    __shared__ double bsc;
    __shared__ int    bcl;

    const int total = g_refine_cnt;
    for (int r = blockIdx.x; r < total; r += gridDim.x) {
        const int   s     = g_refine_list[r];
        const float thr   = g_thr[s];
        const int   apred = g_pred[s];
        const __half* srow = g_scores + (size_t)s * NCP;

        if (tid == 0) { cnt = 1; cand[0] = apred; bsc = -1e300; bcl = 1 << 30; }
        __syncthreads();
        for (int j = tid; j < NC; j += 256) {
            if (__half2float(srow[j]) >= thr && j != apred) {
                int p = atomicAdd(&cnt, 1);
                if (p < 33) cand[p] = j;
            }
        }
        __syncthreads();

        const int nc = (cnt < 33) ? cnt : 33;
        const float* xr = x + (size_t)s * ND;
        for (int ci = 0; ci < nc; ci++) {
            const int cls = cand[ci];
            const float* mr = means + (size_t)cls * ND;
            double part = 0.0;
            #pragma unroll
            for (int k = 0; k < ND / 256; k++) {
                int e = tid + k * 256;
                part += (double)xr[e] * (double)mr[e];
            }
            #pragma unroll
            for (int o = 16; o > 0; o >>= 1)
                part += __shfl_down_sync(0xffffffffu, part, o);
            if ((tid & 31) == 0) red[tid >> 5] = part;
            __syncthreads();
            if (tid == 0) {
                double tot = 0.0;
                #pragma unroll
                for (int w = 0; w < 8; w++) tot += red[w];
                if (tot > bsc || (tot == bsc && cls < bcl)) { bsc = tot; bcl = cls; }
            }
            __syncthreads();
        }
        if (tid == 0) out[(size_t)s * NC + bcl] = 1.0f;
        __syncthreads();
    }
}

// ---------------- launch ----------------------------------------------------
extern "C" void kernel_launch(void* const* d_in, const int* in_sizes, int n_in,
                              void* d_out, int out_size) {
    const float* x     = (const float*)d_in[0];
    const float* means = (const float*)d_in[1];
    float* out = (float*)d_out;

    cudaFuncSetAttribute(gemm_mma7_kernel,
                         cudaFuncAttributeMaxDynamicSharedMemorySize, SMEM_TOTAL);

    cvt_x_kernel<<<(NS * (size_t)ND / 8) / 256, 256>>>(          // launch 1
        reinterpret_cast<const float4*>(x));
    cvt_m_kernel<<<((size_t)NCP * ND / 8) / 256, 256>>>(         // launch 2
        reinterpret_cast<const float4*>(means));
    zero_out_kernel<<<2048, 256>>>(reinterpret_cast<float4*>(out)); // launch 3
    gemm_mma7_kernel<<<dim3(NCP / BN, NS / BM), 256, SMEM_TOTAL>>>(); // launch 4 (ncu)
    argmax_combine_kernel<<<NS / 256, 256>>>(out);               // launch 5
    refine_kernel<<<512, 256>>>(x, means, out);                  // launch 6
}

// round 12
// speedup vs baseline: 1.0530x; 1.0530x over previous
#include <cuda_runtime.h>
#include <cuda_bf16.h>
#include <cuda_fp16.h>
#include <stdint.h>
#include <math.h>

#define NS 16384
#define ND 2048
#define NC 1000
#define NCP 1024

#define MARGIN 1.5f

// GEMM tiling: 128x128 block, 8 warps (4x2), warp tile 32x64, 2 CTAs/SM
#define BM 128
#define BN 128
#define BK 64                  // K per chunk: 128 bytes/row (SW128 atom)
#define KCHUNKS (ND / BK)      // 32
#define STAGES 3
#define A_TILE_BYTES (BM * BK * 2)   // 16384
#define B_TILE_BYTES (BN * BK * 2)   // 16384
#define STAGE_BYTES (A_TILE_BYTES + B_TILE_BYTES)  // 32768
#define SMEM_TOTAL (STAGES * STAGE_BYTES + 1024)

#define NBN (NCP / BN)         // 8 partials per row

// out-zeroing slice per GEMM CTA: NS*NC/1024 = 16000 floats = 4000 float4
#define ZERO_F4_PER_CTA 4000

// ---------------- scratch (static device globals) ---------------------------
__device__ __nv_bfloat16 g_xb[(size_t)NS * ND];    // tiled: [bm][kt][128x64 SW128]
__device__ __nv_bfloat16 g_mb[(size_t)NCP * ND];   // tiled: [bn][kt][128x64 SW128]
__device__ __half        g_scores[(size_t)NS * NCP];
__device__ float         g_pmax[(size_t)NS * NBN];
__device__ float         g_psnd[(size_t)NS * NBN];
__device__ int           g_pidx[(size_t)NS * NBN];
__device__ int           g_pred[NS];
__device__ float         g_thr[NS];
__device__ int           g_refine_list[NS];
__device__ int           g_refine_cnt;

// ---------------- helpers ----------------------------------------------------
__device__ __forceinline__ uint32_t smem_u32(const void* p) {
    return (uint32_t)__cvta_generic_to_shared(p);
}
__host__ __device__ __forceinline__ uint32_t sw128(uint32_t off) {
    return off ^ ((off >> 3) & 0x70);
}
__device__ __forceinline__ void cp16(uint32_t dst, const void* src) {
    asm volatile("cp.async.cg.shared.global [%0], [%1], 16;"
                 :: "r"(dst), "l"(src) : "memory");
}
__device__ __forceinline__ void cp_commit() {
    asm volatile("cp.async.commit_group;" ::: "memory");
}
template <int N>
__device__ __forceinline__ void cp_wait() {
    asm volatile("cp.async.wait_group %0;" :: "n"(N) : "memory");
}
__device__ __forceinline__ void ldsm_x4(uint32_t& r0, uint32_t& r1, uint32_t& r2,
                                        uint32_t& r3, uint32_t addr) {
    asm volatile("ldmatrix.sync.aligned.m8n8.x4.shared.b16 {%0,%1,%2,%3}, [%4];\n"
                 : "=r"(r0), "=r"(r1), "=r"(r2), "=r"(r3) : "r"(addr));
}
__device__ __forceinline__ void mma_bf16(float* c, const uint32_t* a, const uint32_t* b) {
    asm volatile(
        "mma.sync.aligned.m16n8k16.row.col.f32.bf16.bf16.f32 "
        "{%0,%1,%2,%3}, {%4,%5,%6,%7}, {%8,%9}, {%0,%1,%2,%3};\n"
        : "+f"(c[0]), "+f"(c[1]), "+f"(c[2]), "+f"(c[3])
        : "r"(a[0]), "r"(a[1]), "r"(a[2]), "r"(a[3]), "r"(b[0]), "r"(b[1]));
}
// combine (max, idx, second) partials; prefer larger val, then smaller idx
__device__ __forceinline__ void comb(float& m, int& id, float& s,
                                     float om, int oid, float os) {
    if (om > m || (om == m && oid < id)) {
        s = fmaxf(m, os); m = om; id = oid;
    } else {
        s = fmaxf(s, om);
    }
}

// ---------------- merged convert kernel (x then means) ----------------------
// x chunks: g in [0, NS*ND/8); means chunks: g-XCHUNKS in [0, NCP*ND/8).
#define XCHUNKS (NS * (size_t)ND / 8)     // 4,194,304
#define MCHUNKS ((size_t)NCP * ND / 8)    // 524,288

__global__ __launch_bounds__(256) void cvt_all_kernel(const float4* __restrict__ x,
                                                      const float4* __restrict__ m) {
    size_t g = (size_t)blockIdx.x * 256 + threadIdx.x;
    if (g < XCHUNKS) {
        uint32_t gg = (uint32_t)g;
        uint32_t tile = gg >> 10;                  // [bm(128)][kt(32)]
        uint32_t w    = gg & 1023;
        uint32_t tm = tile >> 5, tk = tile & 31;
        uint32_t r  = w >> 3, cgrp = w & 7;
        uint32_t row = tm * 128 + r;
        size_t src = (size_t)row * 512 + tk * 16 + cgrp * 2;
        float4 v0 = x[src];
        float4 v1 = x[src + 1];
        __nv_bfloat162 b0 = __floats2bfloat162_rn(v0.x, v0.y);
        __nv_bfloat162 b1 = __floats2bfloat162_rn(v0.z, v0.w);
        __nv_bfloat162 b2 = __floats2bfloat162_rn(v1.x, v1.y);
        __nv_bfloat162 b3 = __floats2bfloat162_rn(v1.z, v1.w);
        uint4 q;
        q.x = *reinterpret_cast<uint32_t*>(&b0);
        q.y = *reinterpret_cast<uint32_t*>(&b1);
        q.z = *reinterpret_cast<uint32_t*>(&b2);
        q.w = *reinterpret_cast<uint32_t*>(&b3);
        *reinterpret_cast<uint4*>((char*)g_xb + (size_t)tile * A_TILE_BYTES +
                                  sw128(w * 16)) = q;
        if (gg == 0) g_refine_cnt = 0;
    } else {
        uint32_t gg = (uint32_t)(g - XCHUNKS);
        uint32_t tile = gg >> 10;                  // [bn(8)][kt(32)]
        uint32_t w    = gg & 1023;
        uint32_t tb = tile >> 5, tk = tile & 31;
        uint32_t r  = w >> 3, cgrp = w & 7;
        uint32_t row = tb * 128 + r;
        float4 v0 = make_float4(0.f, 0.f, 0.f, 0.f), v1 = v0;
        if (row < NC) {
            size_t src = (size_t)row * 512 + tk * 16 + cgrp * 2;
            v0 = m[src];
            v1 = m[src + 1];
        }
        __nv_bfloat162 b0 = __floats2bfloat162_rn(v0.x, v0.y);
        __nv_bfloat162 b1 = __floats2bfloat162_rn(v0.z, v0.w);
        __nv_bfloat162 b2 = __floats2bfloat162_rn(v1.x, v1.y);
        __nv_bfloat162 b3 = __floats2bfloat162_rn(v1.z, v1.w);
        uint4 q;
        q.x = *reinterpret_cast<uint32_t*>(&b0);
        q.y = *reinterpret_cast<uint32_t*>(&b1);
        q.z = *reinterpret_cast<uint32_t*>(&b2);
        q.w = *reinterpret_cast<uint32_t*>(&b3);
        *reinterpret_cast<uint4*>((char*)g_mb + (size_t)tile * B_TILE_BYTES +
                                  sw128(w * 16)) = q;
    }
}

// ---------------- GEMM: 128x128 block, 8 warps 4x2, warp 32x64 --------------
// Cross-chunk fragment prefetch + fused output zeroing in the prologue
// (64 MB of STG hidden under the tensor-bound mainloop's idle DRAM).
__global__ __launch_bounds__(256, 2) void gemm_mma8_kernel(float4* __restrict__ out) {
    extern __shared__ char smem[];
    const uint32_t sb = (smem_u32(smem) + 1023u) & ~1023u;

    const int tid  = threadIdx.x;
    const int lane = tid & 31;
    const int wid  = tid >> 5;
    const int wm   = wid >> 1;   // 0..3 -> 32-row slab
    const int wn   = wid & 1;    // 0..1 -> 64-col slab
    const int bn   = blockIdx.x; // 0..7
    const int bm   = blockIdx.y; // 0..127

    const char* gA = (const char*)g_xb + (size_t)bm * KCHUNKS * A_TILE_BYTES;
    const char* gB = (const char*)g_mb + (size_t)bn * KCHUNKS * B_TILE_BYTES;

    auto load_stage = [&](int s, int kt) {
        uint32_t Ad = sb + s * STAGE_BYTES;
        const char* Asrc = gA + (size_t)kt * A_TILE_BYTES;
        #pragma unroll
        for (int i = 0; i < 4; i++) {
            int ch = tid + i * 256;
            cp16(Ad + ch * 16, Asrc + ch * 16);
        }
        uint32_t Bd = Ad + A_TILE_BYTES;
        const char* Bsrc = gB + (size_t)kt * B_TILE_BYTES;
        #pragma unroll
        for (int i = 0; i < 4; i++) {
            int ch = tid + i * 256;
            cp16(Bd + ch * 16, Bsrc + ch * 16);
        }
    };

    float acc[2][8][4];
    #pragma unroll
    for (int i = 0; i < 2; i++)
        #pragma unroll
        for (int j = 0; j < 8; j++)
            #pragma unroll
            for (int k = 0; k < 4; k++) acc[i][j][k] = 0.f;

    load_stage(0, 0); cp_commit();
    load_stage(1, 1); cp_commit();

    // fused zero of this CTA's out slice (overlaps the cp.async prefetch)
    {
        const int cta = bm * NBN + bn;               // 0..1023
        float4* z = out + (size_t)cta * ZERO_F4_PER_CTA;
        const float4 zf = make_float4(0.f, 0.f, 0.f, 0.f);
        #pragma unroll
        for (int i = 0; i < 16; i++) {
            int ch = tid + i * 256;
            if (ch < ZERO_F4_PER_CTA) z[ch] = zf;
        }
    }

    const int a_row = wm * 32 + (lane & 15);
    const int a_kb  = ((lane >> 4) << 3) * 2;
    const int b_row = wn * 64 + ((lane >> 4) << 3) + (lane & 7);
    const int b_kb  = (((lane >> 3) & 1) << 3) * 2;

    uint32_t afr[2][2][4];
    uint32_t bfr[2][8][2];

    auto frag_load = [&](uint32_t Ab, uint32_t Bb, int ks, int buf) {
        #pragma unroll
        for (int mt = 0; mt < 2; mt++) {
            uint32_t off = (uint32_t)((a_row + mt * 16) * 128 + ks * 32 + a_kb);
            ldsm_x4(afr[buf][mt][0], afr[buf][mt][1], afr[buf][mt][2],
                    afr[buf][mt][3], Ab + sw128(off));
        }
        #pragma unroll
        for (int nb = 0; nb < 4; nb++) {
            uint32_t off = (uint32_t)((b_row + nb * 16) * 128 + ks * 32 + b_kb);
            uint32_t r0, r1, r2, r3;
            ldsm_x4(r0, r1, r2, r3, Bb + sw128(off));
            bfr[buf][nb * 2 + 0][0] = r0; bfr[buf][nb * 2 + 0][1] = r1;
            bfr[buf][nb * 2 + 1][0] = r2; bfr[buf][nb * 2 + 1][1] = r3;
        }
    };

    // stage 0 ready for everyone, then preload (kt=0, ks=0) fragments
    cp_wait<1>();
    __syncthreads();
    frag_load(sb, sb + A_TILE_BYTES, 0, 0);

    for (int kt = 0; kt < KCHUNKS; kt++) {
        // safe: all warps passed the ks=3 barrier of iter kt-1, so nobody is
        // still reading stage (kt-1)%3, which (kt+2)%3 aliases.
        if (kt + 2 < KCHUNKS) { load_stage((kt + 2) % STAGES, kt + 2); cp_commit(); }

        const uint32_t Ab  = sb + (kt % STAGES) * STAGE_BYTES;
        const uint32_t Bb  = Ab + A_TILE_BYTES;
        const uint32_t Abn = sb + ((kt + 1) % STAGES) * STAGE_BYTES;
        const uint32_t Bbn = Abn + A_TILE_BYTES;

        #pragma unroll
        for (int ks = 0; ks < 4; ks++) {
            const int cur = ks & 1;
            if (ks < 3) {
                frag_load(Ab, Bb, ks + 1, cur ^ 1);
            } else if (kt + 1 < KCHUNKS) {
                // pending groups here: {kt+1, kt+2} (kt+2 absent on last iters)
                if (kt == KCHUNKS - 2) cp_wait<0>(); else cp_wait<1>();
                __syncthreads();   // make all threads' stage-(kt+1) copies visible
                frag_load(Abn, Bbn, 0, cur ^ 1);
            }
            #pragma unroll
            for (int mt = 0; mt < 2; mt++)
                #pragma unroll
                for (int nt = 0; nt < 8; nt++)
                    mma_bf16(acc[mt][nt], afr[cur][mt], bfr[cur][nt]);
        }
    }

    // ---------------- epilogue: store fp16 scores + per-row (max,idx,second) -
    #pragma unroll
    for (int mt = 0; mt < 2; mt++) {
        #pragma unroll
        for (int nt = 0; nt < 8; nt++) {
            int row = bm * BM + wm * 32 + mt * 16 + (lane >> 2);
            int col = bn * BN + wn * 64 + nt * 8 + ((lane & 3) << 1);
            *reinterpret_cast<__half2*>(&g_scores[(size_t)row * NCP + col]) =
                __floats2half2_rn(acc[mt][nt][0], acc[mt][nt][1]);
            *reinterpret_cast<__half2*>(&g_scores[(size_t)(row + 8) * NCP + col]) =
                __floats2half2_rn(acc[mt][nt][2], acc[mt][nt][3]);
        }
    }

    __syncthreads();   // stage buffers dead; reuse smem for partial reduction
    float* pm = reinterpret_cast<float*>(smem);        // [2][128]
    float* ps = pm + 256;                              // [2][128]
    int*   pi = reinterpret_cast<int*>(ps + 256);      // [2][128]

    const int cbase = bn * BN + wn * 64 + ((lane & 3) << 1);
    #pragma unroll
    for (int mt = 0; mt < 2; mt++) {
        #pragma unroll
        for (int h = 0; h < 2; h++) {
            float m = -INFINITY, s = -INFINITY;
            int   id = 0;
            #pragma unroll
            for (int nt = 0; nt < 8; nt++) {
                #pragma unroll
                for (int e = 0; e < 2; e++) {
                    int   col = cbase + nt * 8 + e;
                    float v   = acc[mt][nt][h * 2 + e];
                    if (col >= NC) v = -INFINITY;
                    if (v > m) { s = m; m = v; id = col; }
                    else if (v > s) s = v;
                }
            }
            // quad reduce across the 4 lanes sharing this row
            #pragma unroll
            for (int x = 1; x <= 2; x <<= 1) {
                float om = __shfl_xor_sync(0xffffffffu, m, x);
                int   oi = __shfl_xor_sync(0xffffffffu, id, x);
                float os = __shfl_xor_sync(0xffffffffu, s, x);
                comb(m, id, s, om, oi, os);
            }
            if ((lane & 3) == 0) {
                int rl = wm * 32 + mt * 16 + h * 8 + (lane >> 2);
                pm[wn * 128 + rl] = m;
                ps[wn * 128 + rl] = s;
                pi[wn * 128 + rl] = id;
            }
        }
    }
    __syncthreads();

    if (tid < 128) {
        float m = pm[tid];      int id = pi[tid];      float s = ps[tid];
        comb(m, id, s, pm[128 + tid], pi[128 + tid], ps[128 + tid]);
        size_t o = (size_t)(bm * BM + tid) * NBN + bn;
        g_pmax[o] = m; g_psnd[o] = s; g_pidx[o] = id;
    }
}

// ---------------- combine partials -> pred/thr + write unflagged one-hot ----
__global__ __launch_bounds__(256) void argmax_combine_kernel(float* __restrict__ out) {
    const int s = blockIdx.x * 256 + threadIdx.x;
    if (s >= NS) return;
    const size_t base = (size_t)s * NBN;
    float m = g_pmax[base];  int id = g_pidx[base];  float snd = g_psnd[base];
    #pragma unroll
    for (int p = 1; p < NBN; p++)
        comb(m, id, snd, g_pmax[base + p], g_pidx[base + p], g_psnd[base + p]);

    const float thr = m - MARGIN;
    if (snd >= thr) {
        g_pred[s] = id;
        g_thr[s]  = thr;
        int p = atomicAdd(&g_refine_cnt, 1);
        g_refine_list[p] = s;
    } else {
        out[(size_t)s * NC + id] = 1.0f;   // no competitor within margin
    }
}

// ---------------- exact fp64 refinement + one-hot for flagged samples -------
__global__ __launch_bounds__(256) void refine_kernel(
    const float* __restrict__ x, const float* __restrict__ means,
    float* __restrict__ out) {
    const int tid = threadIdx.x;
    __shared__ int    cnt;
    __shared__ int    cand[33];
    __shared__ double red[8];
    __shared__ double bsc;
    __shared__ int    bcl;

    const int total = g_refine_cnt;
    for (int r = blockIdx.x; r < total; r += gridDim.x) {
        const int   s     = g_refine_list[r];
        const float thr   = g_thr[s];
        const int   apred = g_pred[s];
        const __half* srow = g_scores + (size_t)s * NCP;

        if (tid == 0) { cnt = 1; cand[0] = apred; bsc = -1e300; bcl = 1 << 30; }
        __syncthreads();
        for (int j = tid; j < NC; j += 256) {
            if (__half2float(srow[j]) >= thr && j != apred) {
                int p = atomicAdd(&cnt, 1);
                if (p < 33) cand[p] = j;
            }
        }
        __syncthreads();

        const int nc = (cnt < 33) ? cnt : 33;
        const float* xr = x + (size_t)s * ND;
        for (int ci = 0; ci < nc; ci++) {
            const int cls = cand[ci];
            const float* mr = means + (size_t)cls * ND;
            double part = 0.0;
            #pragma unroll
            for (int k = 0; k < ND / 256; k++) {
                int e = tid + k * 256;
                part += (double)xr[e] * (double)mr[e];
            }
            #pragma unroll
            for (int o = 16; o > 0; o >>= 1)
                part += __shfl_down_sync(0xffffffffu, part, o);
            if ((tid & 31) == 0) red[tid >> 5] = part;
            __syncthreads();
            if (tid == 0) {
                double tot = 0.0;
                #pragma unroll
                for (int w = 0; w < 8; w++) tot += red[w];
                if (tot > bsc || (tot == bsc && cls < bcl)) { bsc = tot; bcl = cls; }
            }
            __syncthreads();
        }
        if (tid == 0) out[(size_t)s * NC + bcl] = 1.0f;
        __syncthreads();
    }
}

// ---------------- launch ----------------------------------------------------
extern "C" void kernel_launch(void* const* d_in, const int* in_sizes, int n_in,
                              void* d_out, int out_size) {
    const float* x     = (const float*)d_in[0];
    const float* means = (const float*)d_in[1];
    float* out = (float*)d_out;

    cudaFuncSetAttribute(gemm_mma8_kernel,
                         cudaFuncAttributeMaxDynamicSharedMemorySize, SMEM_TOTAL);

    const int cvt_blocks = (int)((XCHUNKS + MCHUNKS) / 256);
    cvt_all_kernel<<<cvt_blocks, 256>>>(                          // launch 1
        reinterpret_cast<const float4*>(x),
        reinterpret_cast<const float4*>(means));
    gemm_mma8_kernel<<<dim3(NCP / BN, NS / BM), 256, SMEM_TOTAL>>>( // launch 2
        reinterpret_cast<float4*>(out));
    argmax_combine_kernel<<<NS / 256, 256>>>(out);                // launch 3
    refine_kernel<<<512, 256>>>(x, means, out);                   // launch 4 (ncu)
}